// round 4
// baseline (speedup 1.0000x reference)
#include <cuda_runtime.h>
#include <cstdint>

// B=128, N=16384, T=64. Each warp evolves a 512-element register window
// (2 owned slots of 128 elems + 1 full halo slot each side) independently:
// no barriers, no smem. Owned region is always slots 1,2 -> every store is a
// dense, unpredicated, fully-coalesced STG.128. Row-edge warps clamp OOB halo
// loads and re-pin the boundary halo element each step (exact edge padding).
constexpr int N_ELEM   = 16384;
constexpr int NTHREADS = 256;   // 8 warps per CTA
constexpr int OWNED    = 256;   // elements owned per warp
constexpr int NJ       = 4;     // float4 slots per thread (window = 512 elems)

__global__ __launch_bounds__(NTHREADS, 7)
void heat1d_warp_kernel(const float* __restrict__ f0,
                        const float* __restrict__ log_alpha,
                        float* __restrict__ out, int T)
{
    const int tid = threadIdx.x;
    const int l   = tid & 31;
    const int gw  = blockIdx.x * (NTHREADS / 32) + (tid >> 5);
    const int wpr = N_ELEM / OWNED;       // 64 warps per row
    const int b   = gw / wpr;
    const int w   = gw % wpr;

    float alpha = expf(*log_alpha);
    alpha = fminf(fmaxf(alpha, 0.001f), 1.0f);

    const int  wstart    = w * OWNED;
    const int  lbase     = wstart - 128;           // may be <0 / >N-512 at row edges
    const bool edge_left  = (w == 0);
    const bool edge_right = (w == wpr - 1);

    const float* row = f0 + (size_t)b * N_ELEM;
    // Store base: float4 pointer at window start; owned slots are f4 [32,96).
    float4* outw = reinterpret_cast<float4*>(out + (size_t)b * T * N_ELEM) + (lbase >> 2);

    // Load window (slot j, lane l = elements [lbase+128j+4l, +4)). Clamp OOB
    // (only halo slots of the two edge warps).
    float4 v[NJ];
#pragma unroll
    for (int j = 0; j < NJ; j++) {
        const int e0 = lbase + 128 * j + 4 * l;
        if (e0 >= 0 && e0 <= N_ELEM - 4) {
            v[j] = reinterpret_cast<const float4*>(row)[e0 >> 2];
        } else {
            v[j].x = row[min(max(e0 + 0, 0), N_ELEM - 1)];
            v[j].y = row[min(max(e0 + 1, 0), N_ELEM - 1)];
            v[j].z = row[min(max(e0 + 2, 0), N_ELEM - 1)];
            v[j].w = row[min(max(e0 + 3, 0), N_ELEM - 1)];
        }
    }

    // Emit t = 0: two dense stores (slots 1,2).
    __stcs(&outw[32 + l], v[1]);
    __stcs(&outw[64 + l], v[2]);

    const int upsrc = (l + 31) & 31;
    const int dnsrc = (l + 1)  & 31;

    float4* outt = outw;
    for (int t = 1; t < T; t++) {
        outt += N_ELEM / 4;

        float up[NJ], dn[NJ];
#pragma unroll
        for (int j = 0; j < NJ; j++) {
            float us = (l == 31 && j > 0)      ? v[j - 1].w : v[j].w;
            float ds = (l == 0  && j < NJ - 1) ? v[j + 1].x : v[j].x;
            up[j] = __shfl_sync(0xffffffffu, us, upsrc);
            dn[j] = __shfl_sync(0xffffffffu, ds, dnsrc);
        }
        // Window-edge clamp: fake edges are 128 elems from the owned region,
        // staleness travels 1 elem/step (max 63) -> never reaches owned data.
        if (l == 0)  up[0]      = v[0].x;
        if (l == 31) dn[NJ - 1] = v[NJ - 1].w;

#pragma unroll
        for (int j = 0; j < NJ; j++) {
            const float lx = (up[j]  + v[j].y) - 2.0f * v[j].x;
            const float ly = (v[j].x + v[j].z) - 2.0f * v[j].y;
            const float lz = (v[j].y + v[j].w) - 2.0f * v[j].z;
            const float lw = (v[j].z + dn[j] ) - 2.0f * v[j].w;
            v[j].x = fmaf(alpha, lx, v[j].x);
            v[j].y = fmaf(alpha, ly, v[j].y);
            v[j].z = fmaf(alpha, lz, v[j].z);
            v[j].w = fmaf(alpha, lw, v[j].w);
        }

        // Dense owned stores.
        __stcs(&outt[32 + l], v[1]);
        __stcs(&outt[64 + l], v[2]);

        // Row-edge repair: pin the halo element adjacent to the true row edge
        // to the just-computed edge value (reference's edge padding). The rest
        // of the halo slot drifts but only feeds this overwritten element.
        if (edge_left) {   // window pos 127 (slot0 lane31 .w) := element 0 (slot1 lane0 .x)
            const float e0v = __shfl_sync(0xffffffffu, v[1].x, 0);
            if (l == 31) v[0].w = e0v;
        }
        if (edge_right) {  // window pos 384 (slot3 lane0 .x) := element N-1 (slot2 lane31 .w)
            const float eNv = __shfl_sync(0xffffffffu, v[2].w, 31);
            if (l == 0) v[3].x = eNv;
        }
    }
}

extern "C" void kernel_launch(void* const* d_in, const int* in_sizes, int n_in,
                              void* d_out, int out_size)
{
    const float* f0        = (const float*)d_in[0];
    const float* log_alpha = (const float*)d_in[1];
    float*       out       = (float*)d_out;

    const int B = in_sizes[0] / N_ELEM;    // 128
    const int T = out_size / in_sizes[0];  // 64

    const int total_warps = B * (N_ELEM / OWNED);           // 8192
    const int n_blocks    = total_warps / (NTHREADS / 32);  // 1024

    heat1d_warp_kernel<<<n_blocks, NTHREADS>>>(f0, log_alpha, out, T);
}

// round 5
// speedup vs baseline: 1.1538x; 1.1538x over previous
#include <cuda_runtime.h>
#include <cstdint>

// B=128, N=16384, T=64. Each warp independently evolves a 384-element window
// (256 owned + 64-elem halo each side, halo >= T-1=63) entirely in registers.
// No barriers, no smem. Arithmetic uses packed f32x2 (Blackwell FFMA2) to
// halve FMA-pipe issue slots per stored byte.
constexpr int N_ELEM   = 16384;
constexpr int NTHREADS = 128;   // 4 warps per CTA (fine-grained balancing)
constexpr int OWNED    = 256;
constexpr int WIN      = 384;
constexpr int NJ       = 3;     // float4 slots per thread

__device__ __forceinline__ uint64_t pack2(float lo, float hi) {
    uint64_t o; asm("mov.b64 %0, {%1, %2};" : "=l"(o) : "f"(lo), "f"(hi)); return o;
}
__device__ __forceinline__ void unpack2(float& lo, float& hi, uint64_t in) {
    asm("mov.b64 {%0, %1}, %2;" : "=f"(lo), "=f"(hi) : "l"(in));
}
__device__ __forceinline__ uint64_t add2(uint64_t a, uint64_t b) {
    uint64_t r; asm("add.rn.f32x2 %0, %1, %2;" : "=l"(r) : "l"(a), "l"(b)); return r;
}
__device__ __forceinline__ uint64_t fma2(uint64_t a, uint64_t b, uint64_t c) {
    uint64_t r; asm("fma.rn.f32x2 %0, %1, %2, %3;" : "=l"(r) : "l"(a), "l"(b), "l"(c)); return r;
}

__global__ __launch_bounds__(NTHREADS)
void heat1d_warp_kernel(const float* __restrict__ f0,
                        const float* __restrict__ log_alpha,
                        float* __restrict__ out, int T)
{
    const int tid = threadIdx.x;
    const int l   = tid & 31;
    const int gw  = blockIdx.x * (NTHREADS / 32) + (tid >> 5);
    const int wpr = N_ELEM / OWNED;       // 64 warps per row
    const int b   = gw / wpr;
    const int w   = gw % wpr;

    float alpha = expf(*log_alpha);
    alpha = fminf(fmaxf(alpha, 0.001f), 1.0f);
    const uint64_t A2 = pack2(alpha, alpha);
    const uint64_t M2 = pack2(-2.0f, -2.0f);

    // Window: 384 elems = 96 float4, interleaved (lane l holds f4 j*32+l).
    const int wstart = w * OWNED;
    int lbase = wstart - 64;
    if (lbase < 0) lbase = 0;
    if (lbase > N_ELEM - WIN) lbase = N_ELEM - WIN;
    const int s4 = (wstart - lbase) >> 2;   // owned f4 range start: 0, 16, or 32
    const int e4 = s4 + OWNED / 4;

    const float4* inv = reinterpret_cast<const float4*>(f0 + (size_t)b * N_ELEM)
                        + (lbase >> 2);
    float4* outrow    = reinterpret_cast<float4*>(out + (size_t)b * T * N_ELEM)
                        + (lbase >> 2);

    float4 v[NJ];
    bool doSt[NJ];
#pragma unroll
    for (int j = 0; j < NJ; j++) {
        v[j] = inv[j * 32 + l];
        const int f = j * 32 + l;
        doSt[j] = (f >= s4) && (f < e4);
    }

    // Emit t = 0.
#pragma unroll
    for (int j = 0; j < NJ; j++)
        if (doSt[j]) __stcs(&outrow[j * 32 + l], v[j]);

    const int upsrc = (l + 31) & 31;
    const int dnsrc = (l + 1)  & 31;

    float4* outt = outrow;
    for (int t = 1; t < T; t++) {
        outt += N_ELEM / 4;

        // Neighbor exchange: one rotated shuffle per direction per slot.
        float up[NJ], dn[NJ];
#pragma unroll
        for (int j = 0; j < NJ; j++) {
            float us = (l == 31 && j > 0)      ? v[j - 1].w : v[j].w;
            float ds = (l == 0  && j < NJ - 1) ? v[j + 1].x : v[j].x;
            up[j] = __shfl_sync(0xffffffffu, us, upsrc);
            dn[j] = __shfl_sync(0xffffffffu, ds, dnsrc);
        }
        // Window-edge clamp: exact edge padding at true row ends; interior
        // fake-edge staleness (1 elem/step, max 63) never reaches owned data.
        if (l == 0)  up[0]      = v[0].x;
        if (l == 31) dn[NJ - 1] = v[NJ - 1].w;

#pragma unroll
        for (int j = 0; j < NJ; j++) {
            // Packed update: (x,y,z,w) as two f32x2 pairs.
            const uint64_t pP0 = pack2(v[j].x, v[j].y);
            const uint64_t pP1 = pack2(v[j].z, v[j].w);
            const uint64_t pUA = pack2(up[j],  v[j].x);
            const uint64_t pBC = pack2(v[j].y, v[j].z);
            const uint64_t pDN = pack2(v[j].w, dn[j]);
            uint64_t s0 = add2(pUA, pBC);          // (up+y, x+z)
            uint64_t s1 = add2(pBC, pDN);          // (y+w, z+dn)
            s0 = fma2(M2, pP0, s0);                // laplacian pairs
            s1 = fma2(M2, pP1, s1);
            const uint64_t r0 = fma2(A2, s0, pP0); // x + alpha*lap
            const uint64_t r1 = fma2(A2, s1, pP1);
            unpack2(v[j].x, v[j].y, r0);
            unpack2(v[j].z, v[j].w, r1);

            if (doSt[j]) __stcs(&outt[j * 32 + l], v[j]);
        }
    }
}

extern "C" void kernel_launch(void* const* d_in, const int* in_sizes, int n_in,
                              void* d_out, int out_size)
{
    const float* f0        = (const float*)d_in[0];
    const float* log_alpha = (const float*)d_in[1];
    float*       out       = (float*)d_out;

    const int B = in_sizes[0] / N_ELEM;    // 128
    const int T = out_size / in_sizes[0];  // 64

    const int total_warps = B * (N_ELEM / OWNED);           // 8192
    const int n_blocks    = total_warps / (NTHREADS / 32);  // 2048

    heat1d_warp_kernel<<<n_blocks, NTHREADS>>>(f0, log_alpha, out, T);
}